// round 5
// baseline (speedup 1.0000x reference)
#include <cuda_runtime.h>
#include <math.h>

// Problem constants
#define Sv   512
#define Bv   64
#define FINv 512
#define Hv   512
#define G4   2048   // 4*H

// ---------------------------------------------------------------------------
// Scratch: precomputed input-gate term gx[t][b][col] = x_t[b]·W_ih[col] + bias
// ---------------------------------------------------------------------------
__device__ float g_gx[(size_t)Sv * Bv * G4];

// Per-block arrival flags, padded to 32B to keep them in separate sectors.
#define NBLK 128
__device__ unsigned int g_flag[NBLK * 8];

// ---------------------------------------------------------------------------
// Packed fp32x2 helpers (Blackwell FFMA2 path — only reachable via PTX)
// ---------------------------------------------------------------------------
__device__ __forceinline__ void fma2(unsigned long long& acc,
                                     unsigned long long a,
                                     unsigned long long b) {
    asm("fma.rn.f32x2 %0, %1, %2, %0;" : "+l"(acc) : "l"(a), "l"(b));
}
__device__ __forceinline__ float2 unpack2(unsigned long long v) {
    float2 f;
    asm("mov.b64 {%0, %1}, %2;" : "=f"(f.x), "=f"(f.y) : "l"(v));
    return f;
}
__device__ __forceinline__ float fast_sigmoid(float x) {
    return __fdividef(1.f, 1.f + __expf(-x));
}
__device__ __forceinline__ float fast_tanh(float x) {
    return __fdividef(2.f, 1.f + __expf(-2.f * x)) - 1.f;
}

// ===========================================================================
// Phase 1: gx = X[32768,512] @ W_ih^T[512,2048] + (b_ih + b_hh)
// 128x128x16 tile, 256 threads, 8x8 microtile, packed f32x2 FMA.
// ===========================================================================
#define BM 128
#define BN 128
#define BK 16
#define AROW 260
#define BROW 132

__global__ __launch_bounds__(256, 2) void gemm_x_kernel(
    const float* __restrict__ X,     // [32768][512]
    const float* __restrict__ W,     // [2048][512]
    const float* __restrict__ bih,
    const float* __restrict__ bhh)
{
    __shared__ float As[BK * AROW];
    __shared__ float Bs[BK * BROW];

    const int tid = threadIdx.x;
    const int m0  = blockIdx.y * BM;
    const int n0  = blockIdx.x * BN;
    const int tx  = tid & 15;
    const int ty  = tid >> 4;
    const int lr  = tid >> 2;
    const int lc4 = (tid & 3) * 4;

    unsigned long long acc2[8][4];
#pragma unroll
    for (int i = 0; i < 8; i++)
#pragma unroll
        for (int j = 0; j < 4; j++) acc2[i][j] = 0ULL;

    for (int k0 = 0; k0 < FINv; k0 += BK) {
#pragma unroll
        for (int jj = 0; jj < 2; jj++) {
            int r = lr + 64 * jj;
            float4 av = *reinterpret_cast<const float4*>(
                X + (size_t)(m0 + r) * FINv + k0 + lc4);
            reinterpret_cast<float2*>(As + (lc4 + 0) * AROW)[r] = make_float2(av.x, av.x);
            reinterpret_cast<float2*>(As + (lc4 + 1) * AROW)[r] = make_float2(av.y, av.y);
            reinterpret_cast<float2*>(As + (lc4 + 2) * AROW)[r] = make_float2(av.z, av.z);
            reinterpret_cast<float2*>(As + (lc4 + 3) * AROW)[r] = make_float2(av.w, av.w);
            float4 bv = *reinterpret_cast<const float4*>(
                W + (size_t)(n0 + r) * FINv + k0 + lc4);
            Bs[(lc4 + 0) * BROW + r] = bv.x;
            Bs[(lc4 + 1) * BROW + r] = bv.y;
            Bs[(lc4 + 2) * BROW + r] = bv.z;
            Bs[(lc4 + 3) * BROW + r] = bv.w;
        }
        __syncthreads();
#pragma unroll
        for (int k = 0; k < BK; k++) {
            const ulonglong2* ad =
                reinterpret_cast<const ulonglong2*>(As + k * AROW + ty * 16);
            ulonglong2 a01 = ad[0], a23 = ad[1], a45 = ad[2], a67 = ad[3];
            unsigned long long ap[8] = {a01.x, a01.y, a23.x, a23.y,
                                        a45.x, a45.y, a67.x, a67.y};
            const ulonglong2* bd =
                reinterpret_cast<const ulonglong2*>(Bs + k * BROW + tx * 8);
            ulonglong2 b03 = bd[0], b47 = bd[1];
            unsigned long long bp[4] = {b03.x, b03.y, b47.x, b47.y};
#pragma unroll
            for (int i = 0; i < 8; i++)
#pragma unroll
                for (int j = 0; j < 4; j++)
                    fma2(acc2[i][j], ap[i], bp[j]);
        }
        __syncthreads();
    }

    float bsum[8];
#pragma unroll
    for (int j = 0; j < 8; j++) {
        int n = n0 + tx * 8 + j;
        bsum[j] = bih[n] + bhh[n];
    }
#pragma unroll
    for (int i = 0; i < 8; i++) {
        float2 p0 = unpack2(acc2[i][0]);
        float2 p1 = unpack2(acc2[i][1]);
        float2 p2 = unpack2(acc2[i][2]);
        float2 p3 = unpack2(acc2[i][3]);
        size_t row = (size_t)(m0 + ty * 8 + i) * G4 + n0 + tx * 8;
        float4 v0 = make_float4(p0.x + bsum[0], p0.y + bsum[1],
                                p1.x + bsum[2], p1.y + bsum[3]);
        float4 v1 = make_float4(p2.x + bsum[4], p2.y + bsum[5],
                                p3.x + bsum[6], p3.y + bsum[7]);
        *reinterpret_cast<float4*>(&g_gx[row])     = v0;
        *reinterpret_cast<float4*>(&g_gx[row + 4]) = v1;
    }
}

// ===========================================================================
// Phase 2: persistent recurrence kernel. 128 blocks x 256 threads (8 warps).
// Block bx owns hidden units [4bx, 4bx+4) = 16 gate-cols. Each thread:
// 2 cols x 2 batches x full K, packed f32x2; gx folded into accumulators;
// tiny ex exchange; c in registers; padded flag-array grid barrier.
// ===========================================================================
#define HROW 516                        // 516/4=129 f4 per row; 129 % 8 = 1
#define WS_SZ (16 * HROW)               // 8256
#define HS_SZ (64 * HROW)               // 33024
#define EXR   65
#define EX_SZ (16 * EXR)                // 1040
#define SM_FLOATS (WS_SZ + HS_SZ + EX_SZ)   // 42320 floats = 169280 B

__global__ __launch_bounds__(256, 1) void lstm_rec_kernel(
    const float* __restrict__ whh,   // [2048][512]
    float* __restrict__ out)         // [S*B*H hs][S*B*H cs]
{
    extern __shared__ float sm[];
    float* w_s = sm;                 // col c at c*HROW
    float* h_s = sm + WS_SZ;         // batch b at b*HROW
    float* ex  = sm + WS_SZ + HS_SZ; // [16][EXR]

    float* hs_out = out;
    float* cs_out = out + (size_t)Sv * Bv * Hv;

    const int tid = threadIdx.x;
    const int u0  = blockIdx.x * 4;

    // W_hh slice: local col c (0..15): gate=c>>2, unit=c&3
    for (int i = tid; i < 16 * Hv; i += 256) {
        int c = i >> 9, k = i & (Hv - 1);
        int gr = ((c >> 2) * Hv) + u0 + (c & 3);
        w_s[c * HROW + k] = whh[(size_t)gr * Hv + k];
    }

    const unsigned base = *((volatile unsigned*)&g_flag[blockIdx.x * 8]);

    // GEMM mapping: cols {c2, c2+8}, batches {b2, b2+32}
    const int c2 = tid & 7;
    const int b2 = tid >> 3;               // 0..31
    const float* w0 = w_s + c2 * HROW;
    const float* w1 = w_s + (c2 + 8) * HROW;
    const float* h0 = h_s + b2 * HROW;
    const float* h1 = h_s + (b2 + 32) * HROW;
    // gx column indices for the 2 cols (gate = c>>2, unit = c&3)
    const int col_a = ((c2 >> 2) * Hv) + u0 + (c2 & 3);   // c2+8 -> col_a + 1024

    // Elementwise mapping: one (unit,batch) per thread; c kept in register.
    const int u_e = tid & 3;
    const int b_e = tid >> 2;              // 0..63
    float cpv = 0.f;

    __syncthreads();

    for (int t = 0; t < Sv; t++) {
        // ---- prefetch gx (independent of barrier) ----
        const float* gxt = g_gx + (size_t)t * (Bv * G4);
        float gx00 = __ldg(gxt + (size_t)b2 * G4 + col_a);
        float gx01 = __ldg(gxt + (size_t)(b2 + 32) * G4 + col_a);
        float gx10 = __ldg(gxt + (size_t)b2 * G4 + col_a + 1024);
        float gx11 = __ldg(gxt + (size_t)(b2 + 32) * G4 + col_a + 1024);

        // ---- grid barrier: all blocks finished step t-1 ----
        if (t > 0) {
            const unsigned target = base + (unsigned)t;
            bool ok;
            do {
                ok = (tid < NBLK)
                   ? ((int)(*((volatile unsigned*)&g_flag[tid * 8]) - target) >= 0)
                   : true;
            } while (!__syncthreads_and(ok));
            __threadfence();
        }

        // ---- stage h(t-1) into smem ----
        if (t == 0) {
            for (int i = tid; i < HS_SZ; i += 256) h_s[i] = 0.f;
        } else {
            const float* hp = hs_out + (size_t)(t - 1) * Bv * Hv;
#pragma unroll 8
            for (int i = 0; i < 32; i++) {
                int f = tid + 256 * i;                // f4 index, < 8192
                float4 v = __ldcg(reinterpret_cast<const float4*>(hp) + f);
                int row = f >> 7, col4 = f & 127;
                *reinterpret_cast<float4*>(h_s + row * HROW + col4 * 4) = v;
            }
        }
        __syncthreads();

        // ---- recurrent GEMM: 2 cols x 2 batches, K=512, packed f32x2 ----
        unsigned long long a00 = 0ULL, a01 = 0ULL, a10 = 0ULL, a11 = 0ULL;
#pragma unroll 4
        for (int k4 = 0; k4 < Hv / 4; k4++) {
            ulonglong2 wa = *reinterpret_cast<const ulonglong2*>(w0 + 4 * k4);
            ulonglong2 wb = *reinterpret_cast<const ulonglong2*>(w1 + 4 * k4);
            ulonglong2 ha = *reinterpret_cast<const ulonglong2*>(h0 + 4 * k4);
            ulonglong2 hb = *reinterpret_cast<const ulonglong2*>(h1 + 4 * k4);
            fma2(a00, wa.x, ha.x); fma2(a00, wa.y, ha.y);
            fma2(a01, wa.x, hb.x); fma2(a01, wa.y, hb.y);
            fma2(a10, wb.x, ha.x); fma2(a10, wb.y, ha.y);
            fma2(a11, wb.x, hb.x); fma2(a11, wb.y, hb.y);
        }

        // ---- exchange gate pre-activations (gx folded here) ----
        {
            float2 p;
            p = unpack2(a00); ex[c2 * EXR + b2]            = p.x + p.y + gx00;
            p = unpack2(a01); ex[c2 * EXR + b2 + 32]       = p.x + p.y + gx01;
            p = unpack2(a10); ex[(c2 + 8) * EXR + b2]      = p.x + p.y + gx10;
            p = unpack2(a11); ex[(c2 + 8) * EXR + b2 + 32] = p.x + p.y + gx11;
        }
        __syncthreads();

        // ---- LSTM update: one (unit,batch) per thread ----
        {
            float gi = ex[(0  + u_e) * EXR + b_e];
            float gf = ex[(4  + u_e) * EXR + b_e];
            float gg = ex[(8  + u_e) * EXR + b_e];
            float go = ex[(12 + u_e) * EXR + b_e];
            float si = fast_sigmoid(gi);
            float sf = fast_sigmoid(gf);
            float tg = fast_tanh(gg);
            float so = fast_sigmoid(go);
            float cc = sf * cpv + si * tg;
            cpv = cc;
            float hh = so * fast_tanh(cc);
            size_t o = (size_t)t * Bv * Hv + (size_t)b_e * Hv + u0 + u_e;
            __stcg(hs_out + o, hh);
            __stcg(cs_out + o, cc);
        }

        // ---- arrive ----
        if (t < Sv - 1) {
            __threadfence();
            __syncthreads();
            if (tid == 0)
                atomicExch(&g_flag[blockIdx.x * 8], base + (unsigned)t + 1u);
        }
    }
}

// ===========================================================================
// Launch
// ===========================================================================
extern "C" void kernel_launch(void* const* d_in, const int* in_sizes, int n_in,
                              void* d_out, int out_size)
{
    const float* seq  = (const float*)d_in[0];   // [512,64,512]
    const float* w_ih = (const float*)d_in[1];   // [2048,512]
    const float* w_hh = (const float*)d_in[2];   // [2048,512]
    const float* b_ih = (const float*)d_in[3];   // [2048]
    const float* b_hh = (const float*)d_in[4];   // [2048]
    float* out = (float*)d_out;

    const int smem_p2 = SM_FLOATS * (int)sizeof(float);  // 169280 B
    cudaFuncSetAttribute(lstm_rec_kernel,
                         cudaFuncAttributeMaxDynamicSharedMemorySize, smem_p2);

    dim3 g1(G4 / BN, (Sv * Bv) / BM);   // (16, 256)
    gemm_x_kernel<<<g1, 256>>>(seq, w_ih, b_ih, b_hh);
    lstm_rec_kernel<<<NBLK, 256, smem_p2>>>(w_hh, out);
}

// round 6
// speedup vs baseline: 1.3064x; 1.3064x over previous
#include <cuda_runtime.h>
#include <math.h>

// Problem constants
#define Sv   512
#define Bv   64
#define FINv 512
#define Hv   512
#define G4   2048   // 4*H

// ---------------------------------------------------------------------------
// Scratch: precomputed input-gate term gx[t][b][col] = x_t[b]·W_ih[col] + bias
// ---------------------------------------------------------------------------
__device__ float g_gx[(size_t)Sv * Bv * G4];

// Grid-barrier state (generation-based; leftover values across replays are
// harmless because targets are derived from the start-of-launch base).
__device__ unsigned int g_count = 0;
__device__ unsigned int g_gen   = 0;

#define NBLK 128

// ===========================================================================
// Phase 1: gx = X[32768,512] @ W_ih^T[512,2048] + (b_ih + b_hh)
// tf32 tensor cores via mma.sync.m16n8k8. Block tile 128x128, 8 warps,
// warp tile 64x32 (4x4 m16n8k8 frags), BK=32, cvt.rna.tf32 during staging.
// W is stored [n][k] row-major == col-major B: feeds row.col mma directly.
// ===========================================================================
#define P1ROW 36   // 32 k + 4 pad (uint per element); row = 144 B, 16B aligned

__device__ __forceinline__ unsigned cvt_tf32(float x) {
    unsigned u;
    asm("cvt.rna.tf32.f32 %0, %1;" : "=r"(u) : "f"(x));
    return u;
}

__device__ __forceinline__ void mma_tf32(float c[4], const unsigned a[4],
                                         const unsigned b[2]) {
    asm("mma.sync.aligned.m16n8k8.row.col.f32.tf32.tf32.f32 "
        "{%0,%1,%2,%3}, {%4,%5,%6,%7}, {%8,%9}, {%0,%1,%2,%3};"
        : "+f"(c[0]), "+f"(c[1]), "+f"(c[2]), "+f"(c[3])
        : "r"(a[0]), "r"(a[1]), "r"(a[2]), "r"(a[3]),
          "r"(b[0]), "r"(b[1]));
}

__global__ __launch_bounds__(256, 2) void gemm_x_tf32(
    const float* __restrict__ X,     // [32768][512]  (m = t*64 + b)
    const float* __restrict__ W,     // [2048][512]
    const float* __restrict__ bih,
    const float* __restrict__ bhh)
{
    __shared__ unsigned As[128 * P1ROW];   // As[m][k] (tf32 bits)
    __shared__ unsigned Bs[128 * P1ROW];   // Bs[n][k]

    const int tid  = threadIdx.x;
    const int wid  = tid >> 5;
    const int lane = tid & 31;
    const int g    = lane >> 2;      // 0..7
    const int t    = lane & 3;       // 0..3

    const int m0 = blockIdx.y * 128;
    const int n0 = blockIdx.x * 128;
    const int wm = (wid >> 2) * 64;  // warp m offset within block
    const int wn = (wid & 3) * 32;   // warp n offset within block

    // Loader mapping: 256 threads cover 32 rows x 8 float4 per pass, 4 passes.
    const int lr  = tid >> 3;        // 0..31
    const int lc4 = (tid & 7) * 4;   // 0..28

    float acc[4][4][4];
#pragma unroll
    for (int mi = 0; mi < 4; mi++)
#pragma unroll
        for (int nj = 0; nj < 4; nj++)
#pragma unroll
            for (int q = 0; q < 4; q++) acc[mi][nj][q] = 0.f;

    for (int k0 = 0; k0 < FINv; k0 += 32) {
#pragma unroll
        for (int rr = 0; rr < 128; rr += 32) {
            int row = lr + rr;
            float4 av = *reinterpret_cast<const float4*>(
                X + (size_t)(m0 + row) * FINv + k0 + lc4);
            uint4 at = make_uint4(cvt_tf32(av.x), cvt_tf32(av.y),
                                  cvt_tf32(av.z), cvt_tf32(av.w));
            *reinterpret_cast<uint4*>(&As[row * P1ROW + lc4]) = at;
            float4 bv = *reinterpret_cast<const float4*>(
                W + (size_t)(n0 + row) * FINv + k0 + lc4);
            uint4 bt = make_uint4(cvt_tf32(bv.x), cvt_tf32(bv.y),
                                  cvt_tf32(bv.z), cvt_tf32(bv.w));
            *reinterpret_cast<uint4*>(&Bs[row * P1ROW + lc4]) = bt;
        }
        __syncthreads();

#pragma unroll
        for (int kk = 0; kk < 32; kk += 8) {
            unsigned afr[4][4], bfr[4][2];
#pragma unroll
            for (int mi = 0; mi < 4; mi++) {
                int base = (wm + mi * 16 + g) * P1ROW + kk + t;
                afr[mi][0] = As[base];
                afr[mi][1] = As[base + 8 * P1ROW];
                afr[mi][2] = As[base + 4];
                afr[mi][3] = As[base + 8 * P1ROW + 4];
            }
#pragma unroll
            for (int nj = 0; nj < 4; nj++) {
                int bb = (wn + nj * 8 + g) * P1ROW + kk + t;
                bfr[nj][0] = Bs[bb];
                bfr[nj][1] = Bs[bb + 4];
            }
#pragma unroll
            for (int mi = 0; mi < 4; mi++)
#pragma unroll
                for (int nj = 0; nj < 4; nj++)
                    mma_tf32(acc[mi][nj], afr[mi], bfr[nj]);
        }
        __syncthreads();
    }

    // Epilogue: add folded bias, write gx.
#pragma unroll
    for (int nj = 0; nj < 4; nj++) {
        int n = n0 + wn + nj * 8 + 2 * t;
        float bs0 = bih[n] + bhh[n];
        float bs1 = bih[n + 1] + bhh[n + 1];
#pragma unroll
        for (int mi = 0; mi < 4; mi++) {
            int row = m0 + wm + mi * 16 + g;
            float2 v0 = make_float2(acc[mi][nj][0] + bs0, acc[mi][nj][1] + bs1);
            float2 v1 = make_float2(acc[mi][nj][2] + bs0, acc[mi][nj][3] + bs1);
            *reinterpret_cast<float2*>(&g_gx[(size_t)row * G4 + n])       = v0;
            *reinterpret_cast<float2*>(&g_gx[(size_t)(row + 8) * G4 + n]) = v1;
        }
    }
}

// ===========================================================================
// Phase 2: persistent recurrence kernel (R3 structure — best measured).
// 128 blocks x 128 threads; block bx owns hidden units [4bx, 4bx+4)
// (16 gate-cols) x all 64 batches. W_hh slice in smem for the whole kernel;
// h(t-1) staged to smem per step via __ldcg; c(t-1) kept in REGISTERS
// (same thread owns the same (unit,batch) every step); single-flag
// generation barrier between steps.
// ===========================================================================
#define HPAD 516   // 512 + 4: float4-aligned rows, conflict-free reads

__global__ __launch_bounds__(128, 1) void lstm_rec_kernel(
    const float* __restrict__ whh,   // [2048][512]
    float* __restrict__ out)         // [S*B*H hs][S*B*H cs]
{
    extern __shared__ float sm[];
    float* w_s = sm;                       // [16][HPAD]
    float* h_s = sm + 16 * HPAD;           // [64][HPAD]
    float* ex  = sm + (16 + 64) * HPAD;    // [16][68] gate exchange

    float* hs_out = out;
    float* cs_out = out + (size_t)Sv * Bv * Hv;

    const int tid = threadIdx.x;
    const int u0  = blockIdx.x * 4;

    // Load W_hh slice: local col c (0..15) -> gate=c>>2, unit=c&3
    for (int i = tid; i < 16 * Hv; i += 128) {
        int c = i >> 9, k = i & (Hv - 1);
        int gr = ((c >> 2) * Hv) + u0 + (c & 3);
        w_s[c * HPAD + k] = whh[(size_t)gr * Hv + k];
    }

    unsigned bar_base = 0;
    if (tid == 0) bar_base = atomicAdd(&g_gen, 0u);   // stable leftover value

    const int col8 = tid & 7;   // this thread: gate-cols col8 and col8+8
    const int bg   = tid >> 3;  // batches bg, bg+16, bg+32, bg+48
    const float4* w0p = reinterpret_cast<const float4*>(w_s + col8 * HPAD);
    const float4* w1p = reinterpret_cast<const float4*>(w_s + (col8 + 8) * HPAD);
    const float4* hp4[4] = {
        reinterpret_cast<const float4*>(h_s + (size_t)(bg     ) * HPAD),
        reinterpret_cast<const float4*>(h_s + (size_t)(bg + 16) * HPAD),
        reinterpret_cast<const float4*>(h_s + (size_t)(bg + 32) * HPAD),
        reinterpret_cast<const float4*>(h_s + (size_t)(bg + 48) * HPAD)
    };

    // Elementwise mapping: items tid*2, tid*2+1 -> fixed (u,b); c in regs.
    float cpv[2] = {0.f, 0.f};

    __syncthreads();

    for (int t = 0; t < Sv; t++) {
        // ---- stage h(t-1) into smem ----
        if (t == 0) {
            for (int i = tid; i < 64 * HPAD; i += 128) h_s[i] = 0.f;
        } else {
            const float* hp = hs_out + (size_t)(t - 1) * Bv * Hv;
#pragma unroll 16
            for (int j = 0; j < 64; j++) {   // b = j, k4 = tid
                float4 v = __ldcg(reinterpret_cast<const float4*>(hp + (size_t)j * Hv) + tid);
                *reinterpret_cast<float4*>(h_s + (size_t)j * HPAD + 4 * tid) = v;
            }
        }

        // ---- prefetch gx terms (latency hidden behind GEMM) ----
        float gxv[2][4];
        {
            const float* gxt = g_gx + (size_t)t * (Bv * G4);
#pragma unroll
            for (int ci = 0; ci < 2; ci++) {
                int c    = col8 + ci * 8;
                int gcol = ((c >> 2) * Hv) + u0 + (c & 3);
#pragma unroll
                for (int bj = 0; bj < 4; bj++)
                    gxv[ci][bj] = __ldg(gxt + (size_t)(bg + bj * 16) * G4 + gcol);
            }
        }
        __syncthreads();

        // ---- recurrent GEMM: 2 cols x 4 batches per thread, K=512 ----
        float acc[2][4] = {{0.f, 0.f, 0.f, 0.f}, {0.f, 0.f, 0.f, 0.f}};
#pragma unroll 4
        for (int k4 = 0; k4 < Hv / 4; k4++) {
            float4 wa = w0p[k4];
            float4 wb = w1p[k4];
#pragma unroll
            for (int bj = 0; bj < 4; bj++) {
                float4 hv = hp4[bj][k4];
                acc[0][bj] += wa.x * hv.x; acc[0][bj] += wa.y * hv.y;
                acc[0][bj] += wa.z * hv.z; acc[0][bj] += wa.w * hv.w;
                acc[1][bj] += wb.x * hv.x; acc[1][bj] += wb.y * hv.y;
                acc[1][bj] += wb.z * hv.z; acc[1][bj] += wb.w * hv.w;
            }
        }

        // ---- exchange gates through smem ----
#pragma unroll
        for (int ci = 0; ci < 2; ci++) {
            int c = col8 + ci * 8;
#pragma unroll
            for (int bj = 0; bj < 4; bj++)
                ex[c * 68 + bg + bj * 16] = acc[ci][bj] + gxv[ci][bj];
        }
        __syncthreads();

        // ---- elementwise LSTM update: 2 (unit,batch) items per thread ----
        float* ht = hs_out + (size_t)t * Bv * Hv;
        float* ct = cs_out + (size_t)t * Bv * Hv;
#pragma unroll
        for (int r = 0; r < 2; r++) {
            int item = tid * 2 + r;
            int u = item >> 6, b = item & 63;
            float gi = ex[(0 + u)  * 68 + b];
            float gf = ex[(4 + u)  * 68 + b];
            float gg = ex[(8 + u)  * 68 + b];
            float go = ex[(12 + u) * 68 + b];
            float si = 1.f / (1.f + expf(-gi));
            float sf = 1.f / (1.f + expf(-gf));
            float so = 1.f / (1.f + expf(-go));
            float tg = tanhf(gg);
            float cc = sf * cpv[r] + si * tg;
            cpv[r] = cc;
            float hh = so * tanhf(cc);
            __stcg(ht + (size_t)b * Hv + u0 + u, hh);
            __stcg(ct + (size_t)b * Hv + u0 + u, cc);
        }

        // ---- grid barrier between steps (skip after last) ----
        if (t < Sv - 1) {
            __threadfence();
            __syncthreads();
            if (tid == 0) {
                unsigned target = bar_base + (unsigned)t + 1u;
                if (atomicAdd(&g_count, 1u) == NBLK - 1u) {
                    atomicExch(&g_count, 0u);
                    __threadfence();
                    atomicExch(&g_gen, target);   // release
                } else {
                    while ((int)(atomicAdd(&g_gen, 0u) - target) < 0) { }
                }
                __threadfence();
            }
            __syncthreads();
        }
    }
}

// ===========================================================================
// Launch
// ===========================================================================
extern "C" void kernel_launch(void* const* d_in, const int* in_sizes, int n_in,
                              void* d_out, int out_size)
{
    const float* seq  = (const float*)d_in[0];   // [512,64,512]
    const float* w_ih = (const float*)d_in[1];   // [2048,512]
    const float* w_hh = (const float*)d_in[2];   // [2048,512]
    const float* b_ih = (const float*)d_in[3];   // [2048]
    const float* b_hh = (const float*)d_in[4];   // [2048]
    float* out = (float*)d_out;

    const int smem_p2 = (16 * HPAD + 64 * HPAD + 16 * 68) * (int)sizeof(float); // 169472 B
    cudaFuncSetAttribute(lstm_rec_kernel,
                         cudaFuncAttributeMaxDynamicSharedMemorySize, smem_p2);

    dim3 g1(G4 / 128, (Sv * Bv) / 128);   // (16, 256)
    gemm_x_tf32<<<g1, 256>>>(seq, w_ih, b_ih, b_hh);
    lstm_rec_kernel<<<NBLK, 128, smem_p2>>>(w_hh, out);
}